// round 3
// baseline (speedup 1.0000x reference)
#include <cuda_runtime.h>

#define SSTEPS 8
#define NNODES 50000
#define D 128
#define NE 1600000

#define BM 128
#define PAD_A 20   // sA row pitch in floats (80 B, 16B-aligned)

// ---- device scratch (static; no runtime allocation) ----
__device__ __align__(16) int   g_deg[NNODES];
__device__ __align__(16) int   g_cursor[NNODES];
__device__ __align__(16) int   g_rowptr[NNODES + 1];
__device__ __align__(16) int   g_col[NE];
__device__ __align__(16) float g_invdeg[NNODES];
__device__ __align__(16) float g_WT[2 * D * D];                    // [k][j]: k<128 -> W_l, else W_r
__device__ __align__(16) float g_agg[(size_t)SSTEPS * NNODES * D]; // mean aggregation scratch

// ---------------- CSR build ----------------
__global__ void k_init() {
    int i = blockIdx.x * blockDim.x + threadIdx.x;
    if (i < NNODES) { g_deg[i] = 0; g_cursor[i] = 0; }
}

__global__ void k_count(const int* __restrict__ ei) {
    int e = blockIdx.x * blockDim.x + threadIdx.x;
    if (e < NE) {
        int dst = ei[NE + e];           // edge_index row 1 (int32!)
        atomicAdd(&g_deg[dst], 1);
    }
}

// single 256-thread block: exclusive scan of g_deg -> g_rowptr, plus invdeg
__global__ void k_scan() {
    __shared__ int sbuf[256];
    __shared__ int s_carry;
    if (threadIdx.x == 0) s_carry = 0;
    __syncthreads();
    const int nchunk = (NNODES + 255) / 256;
    for (int c = 0; c < nchunk; c++) {
        int idx = c * 256 + threadIdx.x;
        int v = (idx < NNODES) ? g_deg[idx] : 0;
        sbuf[threadIdx.x] = v;
        __syncthreads();
        for (int off = 1; off < 256; off <<= 1) {
            int t = (threadIdx.x >= off) ? sbuf[threadIdx.x - off] : 0;
            __syncthreads();
            sbuf[threadIdx.x] += t;
            __syncthreads();
        }
        int carry = s_carry;
        if (idx < NNODES) {
            g_rowptr[idx] = carry + sbuf[threadIdx.x] - v;   // exclusive
            g_invdeg[idx] = 1.0f / (float)max(v, 1);
        }
        __syncthreads();
        if (threadIdx.x == 255) s_carry = carry + sbuf[255];
        __syncthreads();
    }
    if (threadIdx.x == 0) g_rowptr[NNODES] = s_carry;
}

__global__ void k_fill(const int* __restrict__ ei) {
    int e = blockIdx.x * blockDim.x + threadIdx.x;
    if (e < NE) {
        int src = ei[e];
        int dst = ei[NE + e];
        int pos = atomicAdd(&g_cursor[dst], 1);
        g_col[g_rowptr[dst] + pos] = src;
    }
}

__global__ void k_wt(const float* __restrict__ Wl, const float* __restrict__ Wr) {
    int i = blockIdx.x * blockDim.x + threadIdx.x;
    if (i < 2 * D * D) {
        int k = i / D, j = i % D;
        g_WT[i] = (k < D) ? Wl[j * D + k] : Wr[j * D + (k - D)];
    }
}

// ---------------- gather mean aggregation ----------------
// one warp per node; grid.y = step
__global__ void __launch_bounds__(256) k_agg(const float* __restrict__ input) {
    int gw = (blockIdx.x * blockDim.x + threadIdx.x) >> 5;
    int lane = threadIdx.x & 31;
    if (gw >= NNODES) return;
    int n = gw;
    int s = blockIdx.y;
    const float* bp = input + (size_t)s * NNODES * D + lane * 4;

    int beg = g_rowptr[n];
    int end = g_rowptr[n + 1];
    float ax = 0.f, ay = 0.f, az = 0.f, aw = 0.f;
    int j = beg;
    for (; j + 4 <= end; j += 4) {
        int c0 = g_col[j], c1 = g_col[j + 1], c2 = g_col[j + 2], c3 = g_col[j + 3];
        float4 v0 = *(const float4*)(bp + (size_t)c0 * D);
        float4 v1 = *(const float4*)(bp + (size_t)c1 * D);
        float4 v2 = *(const float4*)(bp + (size_t)c2 * D);
        float4 v3 = *(const float4*)(bp + (size_t)c3 * D);
        ax += v0.x + v1.x + v2.x + v3.x;
        ay += v0.y + v1.y + v2.y + v3.y;
        az += v0.z + v1.z + v2.z + v3.z;
        aw += v0.w + v1.w + v2.w + v3.w;
    }
    for (; j < end; j++) {
        float4 v = *(const float4*)(bp + (size_t)g_col[j] * D);
        ax += v.x; ay += v.y; az += v.z; aw += v.w;
    }
    float inv = g_invdeg[n];
    float4 r = make_float4(ax * inv, ay * inv, az * inv, aw * inv);
    *(float4*)&g_agg[((size_t)s * NNODES + n) * D + lane * 4] = r;
}

// ---------------- GEMM + head ----------------
// xs[s,n,j] = sum_k cat(agg,x)[s,n,k] * WT[k][j] + b_l[j];  ys = xs . W_fc + b_fc
// grid (ceil(N/128), S), 256 threads, tile 128x128, K=256 in chunks of 16
__global__ void __launch_bounds__(256) k_gemm(
    const float* __restrict__ input,
    const float* __restrict__ b_l,
    const float* __restrict__ W_fc,
    const float* __restrict__ b_fc,
    float* __restrict__ out)
{
    __shared__ float sA[BM * PAD_A];   // [m][16] pitch 20
    __shared__ float sW[16 * 128];     // [kl][j]
    __shared__ float sYs[BM];

    const int s   = blockIdx.y;
    const int nb  = blockIdx.x * BM;
    const int tid = threadIdx.x;
    const int tx  = tid & 15;    // j / 8
    const int ty  = tid >> 4;    // m / 8
    const float* xs_base = input + (size_t)s * NNODES * D;
    const float* ag_base = g_agg + (size_t)s * NNODES * D;

    float acc[8][8];
#pragma unroll
    for (int i = 0; i < 8; i++)
#pragma unroll
        for (int jj = 0; jj < 8; jj++) acc[i][jj] = 0.f;

    const int lm  = tid >> 1;          // row this thread stages
    const int lks = (tid & 1) * 8;     // k-offset within chunk

    for (int kc = 0; kc < 16; kc++) {
        // stage A chunk (agg for kc<8, x for kc>=8) and W chunk
        float4 a0 = make_float4(0, 0, 0, 0), a1 = make_float4(0, 0, 0, 0);
        int n = nb + lm;
        if (n < NNODES) {
            const float* src = (kc < 8)
                ? ag_base + (size_t)n * D + kc * 16 + lks
                : xs_base + (size_t)n * D + (kc - 8) * 16 + lks;
            a0 = *(const float4*)src;
            a1 = *(const float4*)(src + 4);
        }
        float4 w0 = *(const float4*)&g_WT[kc * 16 * 128 + tid * 8];
        float4 w1 = *(const float4*)&g_WT[kc * 16 * 128 + tid * 8 + 4];

        __syncthreads();   // previous chunk fully consumed
        *(float4*)&sA[lm * PAD_A + lks]     = a0;
        *(float4*)&sA[lm * PAD_A + lks + 4] = a1;
        *(float4*)&sW[tid * 8]     = w0;
        *(float4*)&sW[tid * 8 + 4] = w1;
        __syncthreads();

#pragma unroll
        for (int kl = 0; kl < 16; kl++) {
            float4 wv0 = *(const float4*)&sW[kl * 128 + tx * 8];
            float4 wv1 = *(const float4*)&sW[kl * 128 + tx * 8 + 4];
            float wv[8] = { wv0.x, wv0.y, wv0.z, wv0.w, wv1.x, wv1.y, wv1.z, wv1.w };
#pragma unroll
            for (int i = 0; i < 8; i++) {
                float a = sA[(ty * 8 + i) * PAD_A + kl];
#pragma unroll
                for (int jj = 0; jj < 8; jj++) acc[i][jj] += a * wv[jj];
            }
        }
    }

    // epilogue: + b_l, write xs, compute ys
    float4 bl0 = *(const float4*)&b_l[tx * 8];
    float4 bl1 = *(const float4*)&b_l[tx * 8 + 4];
    float bl[8] = { bl0.x, bl0.y, bl0.z, bl0.w, bl1.x, bl1.y, bl1.z, bl1.w };
    float4 wf0 = *(const float4*)&W_fc[tx * 8];
    float4 wf1 = *(const float4*)&W_fc[tx * 8 + 4];
    float wf[8] = { wf0.x, wf0.y, wf0.z, wf0.w, wf1.x, wf1.y, wf1.z, wf1.w };

#pragma unroll
    for (int i = 0; i < 8; i++) {
        int m = ty * 8 + i;
        int n = nb + m;
        float p = 0.f;
#pragma unroll
        for (int jj = 0; jj < 8; jj++) {
            acc[i][jj] += bl[jj];
            p += acc[i][jj] * wf[jj];
        }
        for (int off = 8; off > 0; off >>= 1)
            p += __shfl_down_sync(0xffffffffu, p, off, 16);
        if (tx == 0) sYs[m] = p;
        if (n < NNODES) {
            float* op = out + ((size_t)s * NNODES + n) * D + tx * 8;
            *(float4*)op       = make_float4(acc[i][0], acc[i][1], acc[i][2], acc[i][3]);
            *(float4*)(op + 4) = make_float4(acc[i][4], acc[i][5], acc[i][6], acc[i][7]);
        }
    }
    __syncthreads();
    if (tid < BM) {
        int n = nb + tid;
        if (n < NNODES)
            out[(size_t)SSTEPS * NNODES * D + (size_t)s * NNODES + n] = sYs[tid] + b_fc[0];
    }
}

// ---------------- launch ----------------
extern "C" void kernel_launch(void* const* d_in, const int* in_sizes, int n_in,
                              void* d_out, int out_size) {
    const float* input = (const float*)d_in[0];
    const int*   ei    = (const int*)d_in[1];      // int32! (JAX x64 disabled)
    const float* W_l   = (const float*)d_in[2];
    const float* b_l   = (const float*)d_in[3];
    const float* W_r   = (const float*)d_in[4];
    const float* W_fc  = (const float*)d_in[5];
    const float* b_fc  = (const float*)d_in[6];
    float* out = (float*)d_out;

    k_init <<<(NNODES + 255) / 256, 256>>>();
    k_count<<<(NE + 255) / 256, 256>>>(ei);
    k_scan <<<1, 256>>>();
    k_fill <<<(NE + 255) / 256, 256>>>(ei);
    k_wt   <<<(2 * D * D + 255) / 256, 256>>>(W_l, W_r);

    dim3 agrid((NNODES * 32 + 255) / 256, SSTEPS);
    k_agg<<<agrid, 256>>>(input);

    dim3 ggrid((NNODES + BM - 1) / BM, SSTEPS);
    k_gemm<<<ggrid, 256>>>(input, b_l, W_fc, b_fc, out);
}